// round 2
// baseline (speedup 1.0000x reference)
#include <cuda_runtime.h>

#define BB 4
#define RRF 36
#define CCH 3
#define HH 384
#define WW 224
#define KWIN 64
#define SY 321
#define SX 161
#define SXP 168
#define OH 320
#define OW 160
#define NPB (RRF*OH*OW)   /* 1,843,200 per batch */
#define RB1 720           /* 720 blocks * 256 thr * 10 elem = NPB exactly */

__device__ float g_conv[(size_t)BB*RRF*SY*SXP];  // ~31 MB conv scratch
__device__ float g_resz[(size_t)BB*NPB];         // ~29.5 MB resized logits
__device__ float g_pmax[BB*RB1];
__device__ float g_psum[BB*RB1];
__device__ float g_bmax[BB];
__device__ float g_binv[BB];

typedef unsigned long long u64;

__device__ __forceinline__ u64 ffma2(u64 a, u64 b, u64 c){
    u64 d;
    asm("fma.rn.f32x2 %0, %1, %2, %3;" : "=l"(d) : "l"(a), "l"(b), "l"(c));
    return d;
}
__device__ __forceinline__ u64 dup2(float v){
    u64 d; unsigned int u = __float_as_uint(v);
    asm("mov.b64 %0, {%1, %1};" : "=l"(d) : "r"(u));
    return d;
}

// ---------------------------------------------------------------------------
// Direct correlation, interior-only: S[b,f,y',x'] = sum_{c,i,j} L[b,c,y'+i,x'+j]*K[b*36+f,c,i,j]
// y' in [0,321), x' in [0,161)  (all input reads in-bounds for valid outputs)
// Block: 288 thr = 9 filter-groups x (4 rows x 8 xgroups). Thread: 4 filters x 8 x.
// Filters packed in pairs -> fma.rn.f32x2 (full-rate fp32 on B300).
// ---------------------------------------------------------------------------
__global__ __launch_bounds__(288) void conv_kernel(const float* __restrict__ L,
                                                   const float* __restrict__ Kw){
    __shared__ u64  w_sh[18*64];     // 36 filters as 18 (even,odd) pairs x 64 j
    __shared__ float in_sh[4*132];   // 4 rows x 132 cols

    const int b    = blockIdx.z;
    const int y0   = blockIdx.y * 4;
    const int x0   = blockIdx.x * 64;
    const int tid  = threadIdx.x;
    const int fg   = tid >> 5;       // 0..8 : filter group (filters 4fg..4fg+3)
    const int lane = tid & 31;
    const int rowi = lane >> 3;      // 0..3
    const int xg   = lane & 7;       // 0..7
    const int xbase = xg * 8;

    u64 acc0[8], acc1[8];
#pragma unroll
    for (int k = 0; k < 8; k++){ acc0[k] = 0ull; acc1[k] = 0ull; }

    float* w_shf = (float*)w_sh;
    const float* Lb = L  + (size_t)b*CCH*HH*WW;
    const float* Kb = Kw + (size_t)b*RRF*CCH*KWIN*KWIN;

    for (int c = 0; c < CCH; c++){
        for (int i = 0; i < KWIN; i++){
            __syncthreads();
            // stage weights: 36*64 = 2304 floats = 8 per thread, paired layout
#pragma unroll
            for (int t = 0; t < 8; t++){
                int idx = tid + t*288;
                int f = idx >> 6, j = idx & 63;
                float wv = Kb[(((size_t)f*CCH + c)*KWIN + i)*KWIN + j];
                w_shf[(((f>>1)<<6) + j)*2 + (f&1)] = wv;
            }
            // stage input: 4 rows x 132 cols (clamped reads only feed discarded outputs)
            {
                int rr = tid / 132, cc2 = tid - rr*132;
                int gy = min(y0 + rr + i, HH-1);
                int gx = min(x0 + cc2, WW-1);
                in_sh[tid] = Lb[((size_t)c*HH + gy)*WW + gx];
                int t2 = tid + 288;
                if (t2 < 528){
                    int rr2 = t2 / 132, cc3 = t2 - rr2*132;
                    int gy2 = min(y0 + rr2 + i, HH-1);
                    int gx2 = min(x0 + cc3, WW-1);
                    in_sh[t2] = Lb[((size_t)c*HH + gy2)*WW + gx2];
                }
            }
            __syncthreads();

            const u64* wp0 = w_sh + (2*fg)*64;
            const u64* wp1 = wp0 + 64;
            const float* ir = in_sh + rowi*132 + xbase;

            u64 pin[8];
#pragma unroll
            for (int k = 0; k < 8; k++) pin[k] = dup2(ir[k]);

#pragma unroll
            for (int j = 0; j < 64; j++){
                u64 w0 = wp0[j];
                u64 w1 = wp1[j];
#pragma unroll
                for (int k = 0; k < 8; k++) acc0[k] = ffma2(w0, pin[k], acc0[k]);
#pragma unroll
                for (int k = 0; k < 8; k++) acc1[k] = ffma2(w1, pin[k], acc1[k]);
                if (j < 63){
#pragma unroll
                    for (int k = 0; k < 7; k++) pin[k] = pin[k+1];
                    pin[7] = dup2(ir[j + 8]);
                }
            }
        }
    }

    // epilogue: unpack pairs, guarded store
    const int yy = y0 + rowi;
    if (yy < SY){
#pragma unroll
        for (int k = 0; k < 8; k++){
            int xx = x0 + xbase + k;
            if (xx < SX){
                unsigned int lo, hi;
                asm("mov.b64 {%0, %1}, %2;" : "=r"(lo), "=r"(hi) : "l"(acc0[k]));
                int f0 = 4*fg;
                g_conv[(((size_t)(b*RRF + f0  ))*SY + yy)*SXP + xx] = __uint_as_float(lo);
                g_conv[(((size_t)(b*RRF + f0+1))*SY + yy)*SXP + xx] = __uint_as_float(hi);
                asm("mov.b64 {%0, %1}, %2;" : "=r"(lo), "=r"(hi) : "l"(acc1[k]));
                g_conv[(((size_t)(b*RRF + f0+2))*SY + yy)*SXP + xx] = __uint_as_float(lo);
                g_conv[(((size_t)(b*RRF + f0+3))*SY + yy)*SXP + xx] = __uint_as_float(hi);
            }
        }
    }
}

// ---------------------------------------------------------------------------
// Bilinear resize (385,225)->(384,224) sampled only on the crop [32:352)x[32:192),
// written as the final (320,160) grid; per-block max partials for the softmax.
// jax.image.resize: t = (o+0.5)*in/out - 0.5, two-tap triangle weights.
// ---------------------------------------------------------------------------
__global__ void resize_kernel(){
    const int b = blockIdx.y;
    const int base = blockIdx.x * (256*10);
    const float* S = g_conv + (size_t)b*RRF*SY*SXP;
    float lmax = -3.0e38f;
#pragma unroll
    for (int t = 0; t < 10; t++){
        int idx = base + t*256 + threadIdx.x;
        int r   = idx / (OH*OW);
        int rem = idx - r*(OH*OW);
        int oy  = rem / OW;
        int ox  = rem - oy*OW;
        float ty = ((float)(oy + 32) + 0.5f) * (385.0f/384.0f) - 0.5f;
        float tx = ((float)(ox + 32) + 0.5f) * (225.0f/224.0f) - 0.5f;
        float yf = floorf(ty), xf = floorf(tx);
        float fy = ty - yf,    fx = tx - xf;
        int ys = (int)yf - 32, xs = (int)xf - 32;
        const float* p = S + ((size_t)r*SY + ys)*SXP + xs;
        float v00 = p[0], v01 = p[1], v10 = p[SXP], v11 = p[SXP+1];
        float v0 = v00 + fx*(v01 - v00);
        float v1 = v10 + fx*(v11 - v10);
        float v  = v0  + fy*(v1  - v0);
        g_resz[(size_t)b*NPB + idx] = v;
        lmax = fmaxf(lmax, v);
    }
    __shared__ float red[256];
    red[threadIdx.x] = lmax; __syncthreads();
    for (int s = 128; s > 0; s >>= 1){
        if (threadIdx.x < s) red[threadIdx.x] = fmaxf(red[threadIdx.x], red[threadIdx.x+s]);
        __syncthreads();
    }
    if (threadIdx.x == 0) g_pmax[b*RB1 + blockIdx.x] = red[0];
}

__global__ void reduce_max_kernel(){
    const int b = blockIdx.x;
    float m = -3.0e38f;
    for (int i = threadIdx.x; i < RB1; i += 256) m = fmaxf(m, g_pmax[b*RB1 + i]);
    __shared__ float red[256];
    red[threadIdx.x] = m; __syncthreads();
    for (int s = 128; s > 0; s >>= 1){
        if (threadIdx.x < s) red[threadIdx.x] = fmaxf(red[threadIdx.x], red[threadIdx.x+s]);
        __syncthreads();
    }
    if (threadIdx.x == 0) g_bmax[b] = red[0];
}

__global__ void sumexp_kernel(){
    const int b = blockIdx.y;
    const float bm = g_bmax[b];
    const int base = blockIdx.x * (256*10);
    float s = 0.0f;
#pragma unroll
    for (int t = 0; t < 10; t++){
        int idx = base + t*256 + threadIdx.x;
        s += expf(g_resz[(size_t)b*NPB + idx] - bm);
    }
    __shared__ float red[256];
    red[threadIdx.x] = s; __syncthreads();
    for (int st = 128; st > 0; st >>= 1){
        if (threadIdx.x < st) red[threadIdx.x] += red[threadIdx.x + st];
        __syncthreads();
    }
    if (threadIdx.x == 0) g_psum[b*RB1 + blockIdx.x] = red[0];
}

__global__ void reduce_sum_kernel(){
    const int b = blockIdx.x;
    float s = 0.0f;
    for (int i = threadIdx.x; i < RB1; i += 256) s += g_psum[b*RB1 + i];  // fixed order per thread
    __shared__ float red[256];
    red[threadIdx.x] = s; __syncthreads();
    for (int st = 128; st > 0; st >>= 1){
        if (threadIdx.x < st) red[threadIdx.x] += red[threadIdx.x + st];
        __syncthreads();
    }
    if (threadIdx.x == 0) g_binv[b] = 1.0f / red[0];
}

__global__ void final_kernel(float* __restrict__ out){
    const int b = blockIdx.y;
    const float bm  = g_bmax[b];
    const float inv = g_binv[b];
    const int base = blockIdx.x * (256*10);
#pragma unroll
    for (int t = 0; t < 10; t++){
        int idx = base + t*256 + threadIdx.x;
        out[(size_t)b*NPB + idx] = expf(g_resz[(size_t)b*NPB + idx] - bm) * inv;
    }
}

extern "C" void kernel_launch(void* const* d_in, const int* in_sizes, int n_in,
                              void* d_out, int out_size){
    const float* L  = (const float*)d_in[0];   // logits (4,3,384,224)
    const float* Kw = (const float*)d_in[1];   // kernel (144,3,64,64)
    float* out = (float*)d_out;                // (4,36,320,160) f32

    dim3 cgrid(3, 81, 4);          // xtiles, ytiles, batch
    conv_kernel<<<cgrid, 288>>>(L, Kw);

    dim3 egrid(RB1, 4);
    resize_kernel<<<egrid, 256>>>();
    reduce_max_kernel<<<4, 256>>>();
    sumexp_kernel<<<egrid, 256>>>();
    reduce_sum_kernel<<<4, 256>>>();
    final_kernel<<<egrid, 256>>>(out);
}

// round 4
// speedup vs baseline: 6.4001x; 6.4001x over previous
#include <cuda_runtime.h>
#include <math.h>

typedef unsigned long long u64;

#define BB 4
#define RRF 36
#define CCH 3
#define HH 384
#define WW 224
#define KWIN 64
#define SY 321
#define SX 161
#define SXP 168
#define OH 320
#define OW 160
#define NPB (RRF*OH*OW)   /* 1,843,200 per batch */
#define RB1 720

#define NX 224            /* x length / circular conv size */
#define NKB 113           /* rfft bins */
#define KXP 128           /* padded kx stride */
#define NROW_L (BB*CCH*HH)        /* 4608  */
#define NROW_K (BB*RRF*CCH*KWIN)  /* 27648 */
#define NROW_A (BB*RRF*SY)        /* 46224 */
#define IPAIR 84          /* x-pairs produced by inverse (168 x, 161 used) */
#define IPADP 96          /* padded pair stride */

// ---- scratch (device globals; ~155 MB total) ----
__device__ float g_conv[(size_t)BB*RRF*SY*SXP];
__device__ float g_resz[(size_t)BB*NPB];
__device__ float g_pmax[BB*RB1];
__device__ float g_psum[BB*RB1];
__device__ float g_bmax[BB];
__device__ float g_binv[BB];

__device__ float g_Wc[NKB*NX];           // cos(2pi k n/224)
__device__ float g_Ws[NKB*NX];           // sin(2pi k n/224)
__device__ float g_IWc[NKB*IPADP*2];     // paired inverse cos (scaled)
__device__ float g_IWs[NKB*IPADP*2];     // paired inverse -sin (scaled)

__device__ float g_Lre[(size_t)NROW_L*KXP];
__device__ float g_Lim[(size_t)NROW_L*KXP];
__device__ float g_Kre[(size_t)NROW_K*KXP];
__device__ float g_Kim[(size_t)NROW_K*KXP];
__device__ float g_Kni[(size_t)NROW_K*KXP];
__device__ float g_Are[(size_t)NROW_A*KXP];
__device__ float g_Aim[(size_t)NROW_A*KXP];

__device__ __forceinline__ u64 ffma2(u64 a, u64 b, u64 c){
    u64 d;
    asm("fma.rn.f32x2 %0, %1, %2, %3;" : "=l"(d) : "l"(a), "l"(b), "l"(c));
    return d;
}
__device__ __forceinline__ u64 dup2(float v){
    u64 d; unsigned int u = __float_as_uint(v);
    asm("mov.b64 %0, {%1, %1};" : "=l"(d) : "r"(u));
    return d;
}

// ---------------------------------------------------------------------------
// Twiddle tables (recomputed every launch; deterministic)
// ---------------------------------------------------------------------------
__global__ void init_tables(){
    int idx = blockIdx.x*256 + threadIdx.x;
    if (idx < NKB*NX){
        int k = idx / NX, n = idx - k*NX;
        int m = (k*n) % NX;
        double a = (2.0*M_PI*(double)m)/(double)NX;
        g_Wc[idx] = (float)cos(a);
        g_Ws[idx] = (float)sin(a);
    }
    if (idx < NKB*IPADP){
        int k = idx / IPADP, p = idx - k*IPADP;
        float c0=0.f,c1=0.f,s0=0.f,s1=0.f;
        if (p < IPAIR){
            double sc = ((k==0)||(k==NKB-1)) ? (1.0/NX) : (2.0/NX);
            int x0=2*p, x1=2*p+1;
            int m0=(k*x0)%NX, m1=(k*x1)%NX;
            double a0=2.0*M_PI*(double)m0/(double)NX;
            double a1=2.0*M_PI*(double)m1/(double)NX;
            c0=(float)( sc*cos(a0)); c1=(float)( sc*cos(a1));
            s0=(float)(-sc*sin(a0)); s1=(float)(-sc*sin(a1));
        }
        g_IWc[idx*2]=c0; g_IWc[idx*2+1]=c1;
        g_IWs[idx*2]=s0; g_IWs[idx*2+1]=s1;
    }
}

// ---------------------------------------------------------------------------
// Forward DFT of logits rows: Lhat_k = sum_n x[n] e^{-j 2pi k n/224}
// block = 128 threads (one per bin, 113 live), 8 rows per block
// ---------------------------------------------------------------------------
__global__ __launch_bounds__(128) void fwdL(const float* __restrict__ L){
    __shared__ float sx[8*NX];
    const int r0 = blockIdx.x*8;
    const int tid = threadIdx.x;
    for (int t=tid; t<8*NX; t+=128) sx[t] = L[(size_t)r0*NX + t];
    __syncthreads();
    float ar[8], ai[8];
#pragma unroll
    for (int rr=0; rr<8; rr++){ ar[rr]=0.f; ai[rr]=0.f; }
    if (tid < NKB){
        const float* wc = g_Wc + (size_t)tid*NX;
        const float* ws = g_Ws + (size_t)tid*NX;
#pragma unroll 4
        for (int n=0; n<NX; n++){
            float c = wc[n], s = ws[n];
#pragma unroll
            for (int rr=0; rr<8; rr++){
                float x = sx[rr*NX+n];
                ar[rr] = fmaf(x, c, ar[rr]);
                ai[rr] = fmaf(x, s, ai[rr]);
            }
        }
    }
#pragma unroll
    for (int rr=0; rr<8; rr++){
        g_Lre[(size_t)(r0+rr)*KXP + tid] = ar[rr];
        g_Lim[(size_t)(r0+rr)*KXP + tid] = -ai[rr];  // e^{-j}: im = -sum x sin
    }
}

// ---------------------------------------------------------------------------
// Forward DFT of kernel rows (64 taps, zero pad to 224), stored CONJUGATED:
// kr = sum K cos, ki = +sum K sin, kni = -ki
// ---------------------------------------------------------------------------
__global__ __launch_bounds__(128) void fwdK(const float* __restrict__ Kw){
    __shared__ float sx[8*KWIN];
    const int r0 = blockIdx.x*8;
    const int tid = threadIdx.x;
    for (int t=tid; t<8*KWIN; t+=128) sx[t] = Kw[(size_t)r0*KWIN + t];
    __syncthreads();
    float ar[8], ai[8];
#pragma unroll
    for (int rr=0; rr<8; rr++){ ar[rr]=0.f; ai[rr]=0.f; }
    if (tid < NKB){
        const float* wc = g_Wc + (size_t)tid*NX;
        const float* ws = g_Ws + (size_t)tid*NX;
#pragma unroll 4
        for (int n=0; n<KWIN; n++){
            float c = wc[n], s = ws[n];
#pragma unroll
            for (int rr=0; rr<8; rr++){
                float x = sx[rr*KWIN+n];
                ar[rr] = fmaf(x, c, ar[rr]);
                ai[rr] = fmaf(x, s, ai[rr]);
            }
        }
    }
#pragma unroll
    for (int rr=0; rr<8; rr++){
        size_t o = (size_t)(r0+rr)*KXP + tid;
        g_Kre[o] = ar[rr];
        g_Kim[o] = ai[rr];
        g_Kni[o] = -ai[rr];
    }
}

// ---------------------------------------------------------------------------
// Stage C: A[bf,y',kx] = sum_{c,i} Lhat[b,c,y'+i,kx] * KhatConj[bf,c,i,kx]
// block = 256 thr = 64 y-threads (6 consecutive y' each) x 4 kx-pairs (8 kx)
// grid  = (15 kx-blocks [120 kx], 144 bf). f32x2 packs 2 adjacent kx bins.
// 8-slot rotating register window along y gives 1 new L element per tap.
// ---------------------------------------------------------------------------
__global__ __launch_bounds__(256,2) void stageC(){
    __shared__ __align__(16) float sLr[392*8];
    __shared__ __align__(16) float sLi[392*8];
    __shared__ __align__(16) float sKr[KWIN*8];
    __shared__ __align__(16) float sKi[KWIN*8];
    __shared__ __align__(16) float sKn[KWIN*8];

    const int bf  = blockIdx.y;
    const int b   = bf / RRF;
    const int kx0 = blockIdx.x * 8;
    const int tid = threadIdx.x;
    const int kp  = tid & 3;
    const int ty  = tid >> 2;
    const int lb  = 6*ty;
    int vd = SY - lb; if (vd > 6) vd = 6;

    u64 ar[6], ai[6];
#pragma unroll
    for (int d=0; d<6; d++){ ar[d]=0ull; ai[d]=0ull; }

    for (int c=0; c<CCH; c++){
        __syncthreads();
        {
            size_t lbase = ((size_t)(b*CCH+c)*HH)*KXP + kx0;
            for (int t=tid; t<HH*8; t+=256){
                int y = t>>3, col = t&7;
                sLr[t] = g_Lre[lbase + (size_t)y*KXP + col];
                sLi[t] = g_Lim[lbase + (size_t)y*KXP + col];
            }
            size_t kbase = ((size_t)(bf*CCH+c)*KWIN)*KXP + kx0;
            for (int t=tid; t<KWIN*8; t+=256){
                int i = t>>3, col = t&7;
                sKr[t] = g_Kre[kbase + (size_t)i*KXP + col];
                sKi[t] = g_Kim[kbase + (size_t)i*KXP + col];
                sKn[t] = g_Kni[kbase + (size_t)i*KXP + col];
            }
        }
        __syncthreads();
        if (vd > 0){
            const u64* Lr2 = (const u64*)sLr;
            const u64* Li2 = (const u64*)sLi;
            const u64* Kr2 = (const u64*)sKr;
            const u64* Ki2 = (const u64*)sKi;
            const u64* Kn2 = (const u64*)sKn;
            u64 wr[8], wi[8];
#pragma unroll
            for (int s=0; s<8; s++){
                wr[s] = Lr2[(lb+s)*4 + kp];
                wi[s] = Li2[(lb+s)*4 + kp];
            }
#pragma unroll 16
            for (int i=0; i<KWIN; i++){
                u64 kr = Kr2[i*4+kp], ki = Ki2[i*4+kp], kn = Kn2[i*4+kp];
#pragma unroll
                for (int d=0; d<6; d++){
                    int s = (i+d)&7;
                    ar[d] = ffma2(wr[s], kr, ffma2(wi[s], kn, ar[d]));
                    ai[d] = ffma2(wr[s], ki, ffma2(wi[s], kr, ai[d]));
                }
                int s2 = i&7;  // slot of row lb+i, no longer needed
                wr[s2] = Lr2[(lb+i+8)*4 + kp];  // rows <= 389 < 392
                wi[s2] = Li2[(lb+i+8)*4 + kp];
            }
        }
    }
    if (vd > 0){
#pragma unroll
        for (int d=0; d<6; d++){
            if (d < vd){
                size_t row = (size_t)bf*SY + lb + d;
                *(u64*)&g_Are[row*KXP + kx0 + 2*kp] = ar[d];
                *(u64*)&g_Aim[row*KXP + kx0 + 2*kp] = ai[d];
            }
        }
    }
}

// ---------------------------------------------------------------------------
// Stage D: inverse DFT rows -> g_conv[row][x], x = 0..167 (161 valid)
// out[x] = sum_{k<113} re_k*IWc[k][x] + im_k*IWs[k][x]   (Hermitian folded)
// block = 256 = 32 x-pair threads x 8 row-groups (4 rows each) = 32 rows/blk
// ---------------------------------------------------------------------------
#define DR 32
__global__ __launch_bounds__(256) void stageD(){
    __shared__ float sRe[DR*NKB];
    __shared__ float sIm[DR*NKB];
    const int tid = threadIdx.x;
    const int px  = tid & 31;
    const int rg  = tid >> 5;
    const size_t rbase = (size_t)blockIdx.x * DR;

    for (int t=tid; t<DR*NKB; t+=256){
        int rr = t / NKB, k = t - rr*NKB;
        size_t row = rbase + rr;
        float re=0.f, im=0.f;
        if (row < (size_t)NROW_A){
            re = g_Are[row*KXP + k];
            im = g_Aim[row*KXP + k];
        }
        sRe[t]=re; sIm[t]=im;
    }
    __syncthreads();

    const u64* Wc2 = (const u64*)g_IWc;
    const u64* Ws2 = (const u64*)g_IWs;
    u64 acc[4][3];
#pragma unroll
    for (int rr=0; rr<4; rr++)
#pragma unroll
        for (int q=0; q<3; q++) acc[rr][q]=0ull;

    for (int k=0; k<NKB; k++){
        u64 c0=Wc2[k*IPADP+px], c1=Wc2[k*IPADP+px+32], c2=Wc2[k*IPADP+px+64];
        u64 s0=Ws2[k*IPADP+px], s1=Ws2[k*IPADP+px+32], s2=Ws2[k*IPADP+px+64];
#pragma unroll
        for (int rr=0; rr<4; rr++){
            float re = sRe[(rg*4+rr)*NKB + k];
            float im = sIm[(rg*4+rr)*NKB + k];
            u64 re2 = dup2(re), im2 = dup2(im);
            acc[rr][0] = ffma2(re2,c0, ffma2(im2,s0, acc[rr][0]));
            acc[rr][1] = ffma2(re2,c1, ffma2(im2,s1, acc[rr][1]));
            acc[rr][2] = ffma2(re2,c2, ffma2(im2,s2, acc[rr][2]));
        }
    }
#pragma unroll
    for (int rr=0; rr<4; rr++){
        size_t row = rbase + rg*4 + rr;
        if (row < (size_t)NROW_A){
#pragma unroll
            for (int q=0; q<3; q++){
                int p = px + 32*q;
                if (p < IPAIR){
                    unsigned int lo, hi;
                    asm("mov.b64 {%0, %1}, %2;" : "=r"(lo), "=r"(hi) : "l"(acc[rr][q]));
                    g_conv[row*SXP + 2*p    ] = __uint_as_float(lo);
                    g_conv[row*SXP + 2*p + 1] = __uint_as_float(hi);
                }
            }
        }
    }
}

// ---------------------------------------------------------------------------
// Epilogue (unchanged from round 1): bilinear resize on crop + softmax
// ---------------------------------------------------------------------------
__global__ void resize_kernel(){
    const int b = blockIdx.y;
    const int base = blockIdx.x * (256*10);
    const float* S = g_conv + (size_t)b*RRF*SY*SXP;
    float lmax = -3.0e38f;
#pragma unroll
    for (int t = 0; t < 10; t++){
        int idx = base + t*256 + threadIdx.x;
        int r   = idx / (OH*OW);
        int rem = idx - r*(OH*OW);
        int oy  = rem / OW;
        int ox  = rem - oy*OW;
        float ty = ((float)(oy + 32) + 0.5f) * (385.0f/384.0f) - 0.5f;
        float tx = ((float)(ox + 32) + 0.5f) * (225.0f/224.0f) - 0.5f;
        float yf = floorf(ty), xf = floorf(tx);
        float fy = ty - yf,    fx = tx - xf;
        int ys = (int)yf - 32, xs = (int)xf - 32;
        const float* p = S + ((size_t)r*SY + ys)*SXP + xs;
        float v00 = p[0], v01 = p[1], v10 = p[SXP], v11 = p[SXP+1];
        float v0 = v00 + fx*(v01 - v00);
        float v1 = v10 + fx*(v11 - v10);
        float v  = v0  + fy*(v1  - v0);
        g_resz[(size_t)b*NPB + idx] = v;
        lmax = fmaxf(lmax, v);
    }
    __shared__ float red[256];
    red[threadIdx.x] = lmax; __syncthreads();
    for (int s = 128; s > 0; s >>= 1){
        if (threadIdx.x < s) red[threadIdx.x] = fmaxf(red[threadIdx.x], red[threadIdx.x+s]);
        __syncthreads();
    }
    if (threadIdx.x == 0) g_pmax[b*RB1 + blockIdx.x] = red[0];
}

__global__ void reduce_max_kernel(){
    const int b = blockIdx.x;
    float m = -3.0e38f;
    for (int i = threadIdx.x; i < RB1; i += 256) m = fmaxf(m, g_pmax[b*RB1 + i]);
    __shared__ float red[256];
    red[threadIdx.x] = m; __syncthreads();
    for (int s = 128; s > 0; s >>= 1){
        if (threadIdx.x < s) red[threadIdx.x] = fmaxf(red[threadIdx.x], red[threadIdx.x+s]);
        __syncthreads();
    }
    if (threadIdx.x == 0) g_bmax[b] = red[0];
}

__global__ void sumexp_kernel(){
    const int b = blockIdx.y;
    const float bm = g_bmax[b];
    const int base = blockIdx.x * (256*10);
    float s = 0.0f;
#pragma unroll
    for (int t = 0; t < 10; t++){
        int idx = base + t*256 + threadIdx.x;
        s += expf(g_resz[(size_t)b*NPB + idx] - bm);
    }
    __shared__ float red[256];
    red[threadIdx.x] = s; __syncthreads();
    for (int st = 128; st > 0; st >>= 1){
        if (threadIdx.x < st) red[threadIdx.x] += red[threadIdx.x + st];
        __syncthreads();
    }
    if (threadIdx.x == 0) g_psum[b*RB1 + blockIdx.x] = red[0];
}

__global__ void reduce_sum_kernel(){
    const int b = blockIdx.x;
    float s = 0.0f;
    for (int i = threadIdx.x; i < RB1; i += 256) s += g_psum[b*RB1 + i];
    __shared__ float red[256];
    red[threadIdx.x] = s; __syncthreads();
    for (int st = 128; st > 0; st >>= 1){
        if (threadIdx.x < st) red[threadIdx.x] += red[threadIdx.x + st];
        __syncthreads();
    }
    if (threadIdx.x == 0) g_binv[b] = 1.0f / red[0];
}

__global__ void final_kernel(float* __restrict__ out){
    const int b = blockIdx.y;
    const float bm  = g_bmax[b];
    const float inv = g_binv[b];
    const int base = blockIdx.x * (256*10);
#pragma unroll
    for (int t = 0; t < 10; t++){
        int idx = base + t*256 + threadIdx.x;
        out[(size_t)b*NPB + idx] = expf(g_resz[(size_t)b*NPB + idx] - bm) * inv;
    }
}

extern "C" void kernel_launch(void* const* d_in, const int* in_sizes, int n_in,
                              void* d_out, int out_size){
    const float* L  = (const float*)d_in[0];   // logits (4,3,384,224)
    const float* Kw = (const float*)d_in[1];   // kernel (144,3,64,64)
    float* out = (float*)d_out;                // (4,36,320,160) f32

    init_tables<<<99, 256>>>();
    fwdL<<<NROW_L/8, 128>>>(L);
    fwdK<<<NROW_K/8, 128>>>(Kw);
    stageC<<<dim3(15, BB*RRF), 256>>>();
    stageD<<<(NROW_A + DR - 1)/DR, 256>>>();

    dim3 egrid(RB1, 4);
    resize_kernel<<<egrid, 256>>>();
    reduce_max_kernel<<<4, 256>>>();
    sumexp_kernel<<<egrid, 256>>>();
    reduce_sum_kernel<<<4, 256>>>();
    final_kernel<<<egrid, 256>>>(out);
}